// round 1
// baseline (speedup 1.0000x reference)
#include <cuda_runtime.h>

// GNNGUARD: per-edge cosine similarity + threshold + row-L1-normalize + exp.
// Output layout (float32): [row (E) | col (E) | exp(norm_score) (E)]
//
// Pass 1: normalize node features (xn = x / max(||x||, eps)), zero row sums.
// Pass 2: per-edge dot(xn[row], xn[col]) = cosine; threshold; atomic row sum.
// Pass 3: out = exp(score / denom); also emit edge_index as floats.

#define N_NODES_MAX 100000
#define N_EDGES_MAX 1600000
#define D_FEAT 48
#define D_VEC (D_FEAT / 4)   // 12 float4 per row
#define EPS 1e-8f
#define THRESH 0.1f

__device__ float g_xn[(size_t)N_NODES_MAX * D_FEAT];
__device__ float g_rowsum[N_NODES_MAX];
__device__ float g_score[N_EDGES_MAX];

__global__ void normalize_kernel(const float* __restrict__ x, int n) {
    int i = blockIdx.x * blockDim.x + threadIdx.x;
    if (i >= n) return;
    g_rowsum[i] = 0.0f;

    const float4* __restrict__ xr = (const float4*)(x + (size_t)i * D_FEAT);
    float4 v[D_VEC];
    float ss = 0.0f;
#pragma unroll
    for (int k = 0; k < D_VEC; k++) {
        v[k] = __ldg(&xr[k]);
        ss += v[k].x * v[k].x + v[k].y * v[k].y + v[k].z * v[k].z + v[k].w * v[k].w;
    }
    float inv = 1.0f / fmaxf(sqrtf(ss), EPS);

    float4* __restrict__ o = (float4*)(g_xn + (size_t)i * D_FEAT);
#pragma unroll
    for (int k = 0; k < D_VEC; k++) {
        float4 w = v[k];
        w.x *= inv; w.y *= inv; w.z *= inv; w.w *= inv;
        o[k] = w;
    }
}

__global__ void edge_score_kernel(const int* __restrict__ ei, int E) {
    int e = blockIdx.x * blockDim.x + threadIdx.x;
    if (e >= E) return;
    int r = ei[e];
    int c = ei[E + e];

    const float4* __restrict__ a = (const float4*)(g_xn + (size_t)r * D_FEAT);
    const float4* __restrict__ b = (const float4*)(g_xn + (size_t)c * D_FEAT);

    float dot = 0.0f;
#pragma unroll
    for (int k = 0; k < D_VEC; k++) {
        float4 av = a[k];
        float4 bv = b[k];
        dot = fmaf(av.x, bv.x, dot);
        dot = fmaf(av.y, bv.y, dot);
        dot = fmaf(av.z, bv.z, dot);
        dot = fmaf(av.w, bv.w, dot);
    }
    // cosine similarity (features pre-normalized). threshold at 0.1.
    float s = (dot < THRESH) ? 0.0f : dot;
    g_score[e] = s;
    if (s != 0.0f) atomicAdd(&g_rowsum[r], s);
}

__global__ void finalize_kernel(const int* __restrict__ ei,
                                float* __restrict__ out, int E) {
    int i = blockIdx.x * blockDim.x + threadIdx.x;
    if (i < 2 * E) {
        out[i] = (float)ei[i];
    }
    if (i < E) {
        float s = g_score[i];
        float rs = g_rowsum[ei[i]];
        float denom = (rs == 0.0f) ? 1.0f : rs;
        out[2 * E + i] = __expf(s / denom);
    }
}

extern "C" void kernel_launch(void* const* d_in, const int* in_sizes, int n_in,
                              void* d_out, int out_size) {
    const float* x  = (const float*)d_in[0];
    const int*   ei = (const int*)d_in[1];
    float* out = (float*)d_out;

    int n = in_sizes[0] / D_FEAT;   // 100000
    int E = in_sizes[1] / 2;        // 1600000

    normalize_kernel<<<(n + 255) / 256, 256>>>(x, n);
    edge_score_kernel<<<(E + 255) / 256, 256>>>(ei, E);
    finalize_kernel<<<(2 * E + 255) / 256, 256>>>(ei, out, E);
}

// round 2
// speedup vs baseline: 1.9964x; 1.9964x over previous
#include <cuda_runtime.h>

// GNNGUARD: per-edge cosine similarity + threshold + row-L1-normalize + exp.
// Output layout (float32): [row (E) | col (E) | exp(norm_score) (E)]
//
// Pass 1 (norm_kernel):   inv[i] = 1 / max(||x_i||, eps); rowsum[i] = 0.
//                         8 lanes per row -> coalesced 128B-contiguous loads.
// Pass 2 (edge_kernel):   8 lanes per edge gather both endpoint rows of raw x
//                         (L2-resident, 19.2 MB), shuffle-reduce dot, scale by
//                         inv[r]*inv[c], threshold, atomic row-sum.
// Pass 3 (final_kernel):  out = [row, col, exp(score/denom)] fully coalesced.

#define N_NODES_MAX 100000
#define N_EDGES_MAX 1600000
#define D_FEAT 48
#define EPS 1e-8f
#define THRESH 0.1f

__device__ float g_inv[N_NODES_MAX];
__device__ float g_rowsum[N_NODES_MAX];
__device__ float g_score[N_EDGES_MAX];

__device__ __forceinline__ float dot4(float4 a, float4 b) {
    float s = a.x * b.x;
    s = fmaf(a.y, b.y, s);
    s = fmaf(a.z, b.z, s);
    s = fmaf(a.w, b.w, s);
    return s;
}

// 8 lanes per row: lane l loads float4 chunk l, and chunk 8+l if l<4.
__global__ void norm_kernel(const float* __restrict__ x, int n) {
    int row = blockIdx.x * (blockDim.x >> 3) + (threadIdx.x >> 3);
    int l = threadIdx.x & 7;
    if (row >= n) return;

    const float4* __restrict__ xr = (const float4*)(x + (size_t)row * D_FEAT);
    float4 v = __ldg(&xr[l]);
    float ss = dot4(v, v);
    if (l < 4) {
        float4 w = __ldg(&xr[8 + l]);
        ss += dot4(w, w);
    }
    ss += __shfl_down_sync(0xffffffffu, ss, 4, 8);
    ss += __shfl_down_sync(0xffffffffu, ss, 2, 8);
    ss += __shfl_down_sync(0xffffffffu, ss, 1, 8);
    if (l == 0) {
        g_inv[row] = 1.0f / fmaxf(sqrtf(ss), EPS);
        g_rowsum[row] = 0.0f;
    }
}

// 8 lanes per edge: coalesced gather of both 192B endpoint rows.
__global__ void edge_kernel(const float* __restrict__ x,
                            const int* __restrict__ ei, int E) {
    int e = blockIdx.x * (blockDim.x >> 3) + (threadIdx.x >> 3);
    int l = threadIdx.x & 7;
    if (e >= E) return;

    int r = __ldg(&ei[e]);
    int c = __ldg(&ei[E + e]);

    const float4* __restrict__ a = (const float4*)(x + (size_t)r * D_FEAT);
    const float4* __restrict__ b = (const float4*)(x + (size_t)c * D_FEAT);

    float4 a0 = __ldg(&a[l]);
    float4 b0 = __ldg(&b[l]);
    float part = dot4(a0, b0);
    if (l < 4) {
        float4 a1 = __ldg(&a[8 + l]);
        float4 b1 = __ldg(&b[8 + l]);
        part += dot4(a1, b1);
    }
    part += __shfl_down_sync(0xffffffffu, part, 4, 8);
    part += __shfl_down_sync(0xffffffffu, part, 2, 8);
    part += __shfl_down_sync(0xffffffffu, part, 1, 8);

    if (l == 0) {
        float s = part * g_inv[r] * g_inv[c];
        s = (s < THRESH) ? 0.0f : s;
        g_score[e] = s;
        if (s != 0.0f) atomicAdd(&g_rowsum[r], s);
    }
}

__global__ void final_kernel(const int* __restrict__ ei,
                             float* __restrict__ out, int E) {
    int i = blockIdx.x * blockDim.x + threadIdx.x;
    if (i >= E) return;
    int r = __ldg(&ei[i]);
    int c = __ldg(&ei[E + i]);
    float s = g_score[i];
    float rs = g_rowsum[r];
    float denom = (rs == 0.0f) ? 1.0f : rs;
    out[i] = (float)r;
    out[E + i] = (float)c;
    out[2 * E + i] = __expf(s / denom);
}

extern "C" void kernel_launch(void* const* d_in, const int* in_sizes, int n_in,
                              void* d_out, int out_size) {
    const float* x  = (const float*)d_in[0];
    const int*   ei = (const int*)d_in[1];
    float* out = (float*)d_out;

    int n = in_sizes[0] / D_FEAT;   // 100000
    int E = in_sizes[1] / 2;        // 1600000

    // 256 threads = 32 rows/edges per block (8 lanes each)
    norm_kernel<<<(n + 31) / 32, 256>>>(x, n);
    edge_kernel<<<(E + 31) / 32, 256>>>(x, ei, E);
    final_kernel<<<(E + 255) / 256, 256>>>(ei, out, E);
}

// round 3
// speedup vs baseline: 2.2640x; 1.1340x over previous
#include <cuda_runtime.h>
#include <cuda_fp16.h>

// GNNGUARD: per-edge cosine similarity + threshold + row-L1-normalize + exp.
// Output layout (float32): [row (E) | col (E) | exp(norm_score) (E)]
//
// Pass 1 (norm_kernel):  inv[i] = 1/max(||x_i||,eps); xh[i] = fp16(x_i * inv);
//                        rowsum[i] = 0. 8 lanes/row, 2 rows per group (MLP).
// Pass 2 (edge_kernel):  4 lanes/edge gather both 96B fp16 rows (L2-resident),
//                        fp32-accumulated dot = cosine. Edges within +-1.5e-3
//                        of the threshold are recomputed in full fp32 from raw
//                        x (covers fp16 worst-case quantization). Threshold,
//                        atomic row-sum, and write edge_index floats to out.
// Pass 3 (final_kernel): out[2E+i] = exp(score/denom), 4 edges/thread.

#define N_NODES_MAX 100000
#define N_EDGES_MAX 1600000
#define D_FEAT 48
#define EPS 1e-8f
#define THRESH 0.1f
#define BAND 1.5e-3f

__device__ float g_inv[N_NODES_MAX];
__device__ float g_rowsum[N_NODES_MAX];
__device__ float g_score[N_EDGES_MAX];
__device__ __align__(16) __half g_xh[(size_t)N_NODES_MAX * D_FEAT];

__device__ __forceinline__ float dot4(float4 a, float4 b) {
    float s = a.x * b.x;
    s = fmaf(a.y, b.y, s);
    s = fmaf(a.z, b.z, s);
    s = fmaf(a.w, b.w, s);
    return s;
}

__device__ __forceinline__ float dot_h2(unsigned ua, unsigned ub, float s) {
    __half2 ha = *reinterpret_cast<__half2*>(&ua);
    __half2 hb = *reinterpret_cast<__half2*>(&ub);
    float2 fa = __half22float2(ha);
    float2 fb = __half22float2(hb);
    s = fmaf(fa.x, fb.x, s);
    s = fmaf(fa.y, fb.y, s);
    return s;
}

// 8 lanes per row, 2 rows per group (rows g and g+nhalf) for MLP.
__global__ void norm_kernel(const float* __restrict__ x, int n) {
    int nhalf = (n + 1) >> 1;
    int g = blockIdx.x * (blockDim.x >> 3) + (threadIdx.x >> 3);
    int l = threadIdx.x & 7;
    if (g >= nhalf) return;

    int rows[2] = {g, g + nhalf};
    int cnt = (rows[1] < n) ? 2 : 1;

    float4 v0[2], v1[2];
#pragma unroll
    for (int j = 0; j < 2; j++) {
        if (j >= cnt) break;
        const float4* __restrict__ xr = (const float4*)(x + (size_t)rows[j] * D_FEAT);
        v0[j] = __ldg(&xr[l]);
        if (l < 4) v1[j] = __ldg(&xr[8 + l]);
    }

#pragma unroll
    for (int j = 0; j < 2; j++) {
        if (j >= cnt) break;
        int row = rows[j];
        float ss = dot4(v0[j], v0[j]);
        if (l < 4) ss += dot4(v1[j], v1[j]);
        ss += __shfl_xor_sync(0xffffffffu, ss, 4, 8);
        ss += __shfl_xor_sync(0xffffffffu, ss, 2, 8);
        ss += __shfl_xor_sync(0xffffffffu, ss, 1, 8);
        float inv = 1.0f / fmaxf(sqrtf(ss), EPS);
        if (l == 0) {
            g_inv[row] = inv;
            g_rowsum[row] = 0.0f;
        }
        // write fp16 normalized row: lane l covers halves [4l,4l+4) and [32+4l,...)
        __half* hr = g_xh + (size_t)row * D_FEAT;
        {
            __half2 h01 = __floats2half2_rn(v0[j].x * inv, v0[j].y * inv);
            __half2 h23 = __floats2half2_rn(v0[j].z * inv, v0[j].w * inv);
            uint2 w;
            w.x = *reinterpret_cast<unsigned*>(&h01);
            w.y = *reinterpret_cast<unsigned*>(&h23);
            *reinterpret_cast<uint2*>(hr + 4 * l) = w;
        }
        if (l < 4) {
            __half2 h01 = __floats2half2_rn(v1[j].x * inv, v1[j].y * inv);
            __half2 h23 = __floats2half2_rn(v1[j].z * inv, v1[j].w * inv);
            uint2 w;
            w.x = *reinterpret_cast<unsigned*>(&h01);
            w.y = *reinterpret_cast<unsigned*>(&h23);
            *reinterpret_cast<uint2*>(hr + 32 + 4 * l) = w;
        }
    }
}

// 4 lanes per edge: gather both 96B fp16 rows, fp32-accumulated dot.
__global__ void edge_kernel(const float* __restrict__ x,
                            const int* __restrict__ ei,
                            float* __restrict__ out, int E) {
    int g = blockIdx.x * (blockDim.x >> 2) + (threadIdx.x >> 2);
    int l = threadIdx.x & 3;
    if (g >= E) return;

    int r = __ldg(&ei[g]);
    int c = __ldg(&ei[E + g]);

    const uint4* __restrict__ a = (const uint4*)(g_xh + (size_t)r * D_FEAT);
    const uint4* __restrict__ b = (const uint4*)(g_xh + (size_t)c * D_FEAT);

    uint4 a0 = a[l];
    uint4 b0 = b[l];
    float s = 0.0f;
    s = dot_h2(a0.x, b0.x, s);
    s = dot_h2(a0.y, b0.y, s);
    s = dot_h2(a0.z, b0.z, s);
    s = dot_h2(a0.w, b0.w, s);
    if (l < 2) {
        uint4 a1 = a[4 + l];
        uint4 b1 = b[4 + l];
        s = dot_h2(a1.x, b1.x, s);
        s = dot_h2(a1.y, b1.y, s);
        s = dot_h2(a1.z, b1.z, s);
        s = dot_h2(a1.w, b1.w, s);
    }
    s += __shfl_xor_sync(0xffffffffu, s, 1, 4);
    s += __shfl_xor_sync(0xffffffffu, s, 2, 4);
    // all 4 lanes hold approximate cosine

    if (fabsf(s - THRESH) < BAND) {
        // near-threshold: recompute exactly in fp32 from raw x
        const float4* __restrict__ af = (const float4*)(x + (size_t)r * D_FEAT);
        const float4* __restrict__ bf = (const float4*)(x + (size_t)c * D_FEAT);
        float d = 0.0f;
#pragma unroll
        for (int k = 0; k < 3; k++) {
            float4 av = __ldg(&af[l + 4 * k]);
            float4 bv = __ldg(&bf[l + 4 * k]);
            d += dot4(av, bv);
        }
        d += __shfl_xor_sync(0xffffffffu, d, 1, 4);
        d += __shfl_xor_sync(0xffffffffu, d, 2, 4);
        s = d * g_inv[r] * g_inv[c];
    }

    s = (s < THRESH) ? 0.0f : s;
    if (l == 0) {
        g_score[g] = s;
        if (s != 0.0f) atomicAdd(&g_rowsum[r], s);
    } else if (l == 1) {
        out[g] = (float)r;
    } else if (l == 2) {
        out[E + g] = (float)c;
    }
}

__device__ __forceinline__ float dn(float rs) { return (rs == 0.0f) ? 1.0f : rs; }

// 4 edges per thread, vectorized.
__global__ void final_kernel(const int* __restrict__ ei,
                             float* __restrict__ out, int E) {
    int base = (blockIdx.x * blockDim.x + threadIdx.x) * 4;
    if (base >= E) return;
    if (base + 4 <= E) {
        int4 r4 = *(const int4*)(ei + base);
        float4 s4 = *(const float4*)(g_score + base);
        float4 o;
        o.x = __expf(s4.x / dn(g_rowsum[r4.x]));
        o.y = __expf(s4.y / dn(g_rowsum[r4.y]));
        o.z = __expf(s4.z / dn(g_rowsum[r4.z]));
        o.w = __expf(s4.w / dn(g_rowsum[r4.w]));
        *(float4*)(out + 2 * (size_t)E + base) = o;
    } else {
        for (int i = base; i < E; i++) {
            float rs = g_rowsum[__ldg(&ei[i])];
            out[2 * (size_t)E + i] = __expf(g_score[i] / dn(rs));
        }
    }
}

extern "C" void kernel_launch(void* const* d_in, const int* in_sizes, int n_in,
                              void* d_out, int out_size) {
    const float* x  = (const float*)d_in[0];
    const int*   ei = (const int*)d_in[1];
    float* out = (float*)d_out;

    int n = in_sizes[0] / D_FEAT;   // 100000
    int E = in_sizes[1] / 2;        // 1600000

    int nhalf = (n + 1) >> 1;
    norm_kernel<<<(nhalf + 31) / 32, 256>>>(x, n);
    edge_kernel<<<(E + 63) / 64, 256>>>(x, ei, out, E);
    final_kernel<<<((E + 3) / 4 + 255) / 256, 256>>>(ei, out, E);
}